// round 1
// baseline (speedup 1.0000x reference)
#include <cuda_runtime.h>
#include <math.h>

// Problem constants
#define B_  2
#define S_  2048
#define F_  1024
#define H_  16
#define D_  64
#define M_  (B_ * S_)          // 4096 rows
#define BH_ (B_ * H_)          // 32
#define OUT_ELEMS (M_ * F_)    // 4194304
#define ATTN_ELEMS ((size_t)BH_ * S_ * S_)  // 134217728

// ---------------- device scratch (no allocations allowed) ----------------
__device__ float g_xn[OUT_ELEMS];
__device__ float g_q[OUT_ELEMS];
__device__ float g_k[OUT_ELEMS];
__device__ float g_v[OUT_ELEMS];
__device__ float g_ctx[OUT_ELEMS];
__device__ float g_tmp[OUT_ELEMS];
__device__ float2 g_stats[BH_ * S_];
__device__ float g_attn_fallback[ATTN_ELEMS];

// ---------------- LayerNorm: one block per row (1024 cols, 256 thr) ------
__global__ void ln_kernel(const float* __restrict__ x,
                          const float* __restrict__ gamma,
                          const float* __restrict__ beta,
                          float* __restrict__ out) {
    __shared__ float sred[8];
    int row = blockIdx.x;
    int t = threadIdx.x;
    const float4* xr = (const float4*)(x + (size_t)row * F_);
    float4 v = xr[t];

    // mean
    float s = v.x + v.y + v.z + v.w;
    #pragma unroll
    for (int o = 16; o; o >>= 1) s += __shfl_xor_sync(0xffffffffu, s, o);
    if ((t & 31) == 0) sred[t >> 5] = s;
    __syncthreads();
    float tot = 0.f;
    #pragma unroll
    for (int i = 0; i < 8; i++) tot += sred[i];
    float mean = tot * (1.0f / F_);
    __syncthreads();

    // variance
    float dx = v.x - mean, dy = v.y - mean, dz = v.z - mean, dw = v.w - mean;
    float ss = dx*dx + dy*dy + dz*dz + dw*dw;
    #pragma unroll
    for (int o = 16; o; o >>= 1) ss += __shfl_xor_sync(0xffffffffu, ss, o);
    if ((t & 31) == 0) sred[t >> 5] = ss;
    __syncthreads();
    float tot2 = 0.f;
    #pragma unroll
    for (int i = 0; i < 8; i++) tot2 += sred[i];
    float rstd = rsqrtf(tot2 * (1.0f / F_) + 1e-6f);

    float4 g4 = ((const float4*)gamma)[t];
    float4 b4 = ((const float4*)beta)[t];
    float4 o4;
    o4.x = dx * rstd * g4.x + b4.x;
    o4.y = dy * rstd * g4.y + b4.y;
    o4.z = dz * rstd * g4.z + b4.z;
    o4.w = dw * rstd * g4.w + b4.w;
    ((float4*)(out + (size_t)row * F_))[t] = o4;
}

// ---------------- GEMM: C[M,N] = A[M,K] @ W[K,N] + bias (+pos)(+res) -----
// BM=BN=64, BK=16, 256 threads, 4x4 register tile per thread.
__global__ void gemm_kernel(const float* __restrict__ A,
                            const float* __restrict__ W,
                            const float* __restrict__ bias,
                            const float* __restrict__ pos,   // null or [S_, D_]
                            const float* __restrict__ res,   // null or [M_, F_]
                            float* __restrict__ C) {
    __shared__ float As[16][64];
    __shared__ float Bs[16][64];

    int tid = threadIdx.x;
    int tx = tid & 15;            // 0..15
    int ty = tid >> 4;            // 0..15
    int m0 = blockIdx.y * 64;
    int n0 = blockIdx.x * 64;

    float acc[4][4];
    #pragma unroll
    for (int i = 0; i < 4; i++)
        #pragma unroll
        for (int j = 0; j < 4; j++) acc[i][j] = 0.f;

    for (int k0 = 0; k0 < F_; k0 += 16) {
        // load A tile 64x16 -> As[k][m] (transposed)
        #pragma unroll
        for (int idx = tid; idx < 1024; idx += 256) {
            int r = idx >> 4, c = idx & 15;
            As[c][r] = A[(size_t)(m0 + r) * F_ + k0 + c];
        }
        // load W tile 16x64 via float4
        {
            int r = tid >> 4, c = (tid & 15) << 2;
            *(float4*)&Bs[r][c] = *(const float4*)&W[(size_t)(k0 + r) * F_ + n0 + c];
        }
        __syncthreads();

        #pragma unroll
        for (int kk = 0; kk < 16; kk++) {
            float4 a = *(float4*)&As[kk][ty << 2];
            float4 b = *(float4*)&Bs[kk][tx << 2];
            acc[0][0] += a.x*b.x; acc[0][1] += a.x*b.y; acc[0][2] += a.x*b.z; acc[0][3] += a.x*b.w;
            acc[1][0] += a.y*b.x; acc[1][1] += a.y*b.y; acc[1][2] += a.y*b.z; acc[1][3] += a.y*b.w;
            acc[2][0] += a.z*b.x; acc[2][1] += a.z*b.y; acc[2][2] += a.z*b.z; acc[2][3] += a.z*b.w;
            acc[3][0] += a.w*b.x; acc[3][1] += a.w*b.y; acc[3][2] += a.w*b.z; acc[3][3] += a.w*b.w;
        }
        __syncthreads();
    }

    #pragma unroll
    for (int i = 0; i < 4; i++) {
        int row = m0 + (ty << 2) + i;
        int s = row & (S_ - 1);
        #pragma unroll
        for (int j = 0; j < 4; j++) {
            int col = n0 + (tx << 2) + j;
            float val = acc[i][j] + bias[col];
            if (pos) val += pos[(size_t)s * D_ + (col & (D_ - 1))];
            if (res) val += res[(size_t)row * F_ + col];
            C[(size_t)row * F_ + col] = val;
        }
    }
}

// ---------------- attention pass A: per-row online (max, sumexp) ---------
// grid: (S/32, BH), 256 threads. Tile: 32 q-rows, key chunks of 32.
#define QPAD 76
__global__ void attn_stats_kernel(const float* __restrict__ q,
                                  const float* __restrict__ k,
                                  float2* __restrict__ stats) {
    __shared__ float Qs[32][QPAD];
    __shared__ float Ks[32][QPAD];

    int tid = threadIdx.x;
    int bh = blockIdx.y;
    int b = bh >> 4, h = bh & 15;
    int q0 = blockIdx.x * 32;
    const float* qbase = q + (size_t)b * S_ * F_ + h * D_;
    const float* kbase = k + (size_t)b * S_ * F_ + h * D_;

    // load Q tile (32x64) via float4
    #pragma unroll
    for (int idx = tid; idx < 512; idx += 256) {
        int r = idx >> 4, c = (idx & 15) << 2;
        *(float4*)&Qs[r][c] = *(const float4*)&qbase[(size_t)(q0 + r) * F_ + c];
    }
    __syncthreads();

    int qr = tid >> 3;
    int j0 = (tid & 7) << 2;
    int qg = q0 + qr;
    float m = -1e30f, ssum = 0.f;
    const float scale = 0.125f;  // 1/sqrt(64)

    for (int jb = 0; jb <= q0; jb += 32) {
        __syncthreads();
        #pragma unroll
        for (int idx = tid; idx < 512; idx += 256) {
            int r = idx >> 4, c = (idx & 15) << 2;
            *(float4*)&Ks[r][c] = *(const float4*)&kbase[(size_t)(jb + r) * F_ + c];
        }
        __syncthreads();

        float a0 = 0.f, a1 = 0.f, a2 = 0.f, a3 = 0.f;
        #pragma unroll
        for (int kk = 0; kk < 64; kk += 4) {
            float4 qv = *(float4*)&Qs[qr][kk];
            float4 k0v = *(float4*)&Ks[j0 + 0][kk];
            float4 k1v = *(float4*)&Ks[j0 + 1][kk];
            float4 k2v = *(float4*)&Ks[j0 + 2][kk];
            float4 k3v = *(float4*)&Ks[j0 + 3][kk];
            a0 += qv.x*k0v.x + qv.y*k0v.y + qv.z*k0v.z + qv.w*k0v.w;
            a1 += qv.x*k1v.x + qv.y*k1v.y + qv.z*k1v.z + qv.w*k1v.w;
            a2 += qv.x*k2v.x + qv.y*k2v.y + qv.z*k2v.z + qv.w*k2v.w;
            a3 += qv.x*k3v.x + qv.y*k3v.y + qv.z*k3v.z + qv.w*k3v.w;
        }
        float l[4] = {a0 * scale, a1 * scale, a2 * scale, a3 * scale};
        #pragma unroll
        for (int jj = 0; jj < 4; jj++) {
            int j = jb + j0 + jj;
            if (j <= qg) {
                float lv = l[jj];
                if (lv > m) { ssum = ssum * __expf(m - lv) + 1.f; m = lv; }
                else        { ssum += __expf(lv - m); }
            }
        }
    }

    // merge across 8 threads sharing qr (consecutive lanes within warp)
    #pragma unroll
    for (int o = 1; o < 8; o <<= 1) {
        float mo = __shfl_xor_sync(0xffffffffu, m, o);
        float so = __shfl_xor_sync(0xffffffffu, ssum, o);
        float mn = fmaxf(m, mo);
        ssum = ssum * __expf(m - mn) + so * __expf(mo - mn);
        m = mn;
    }
    if ((tid & 7) == 0) stats[bh * S_ + qg] = make_float2(m, ssum);
}

// ---------------- attention pass B: probs + ctx --------------------------
__global__ void attn_ctx_kernel(const float* __restrict__ q,
                                const float* __restrict__ k,
                                const float* __restrict__ v,
                                const float2* __restrict__ stats,
                                float* __restrict__ attn,
                                float* __restrict__ ctx) {
    __shared__ float Qs[32][QPAD];
    __shared__ float Ks[32][QPAD];
    __shared__ float Vs[32][QPAD];
    __shared__ float Ps[32][36];

    int tid = threadIdx.x;
    int bh = blockIdx.y;
    int b = bh >> 4, h = bh & 15;
    int q0 = blockIdx.x * 32;
    const float* qbase = q + (size_t)b * S_ * F_ + h * D_;
    const float* kbase = k + (size_t)b * S_ * F_ + h * D_;
    const float* vbase = v + (size_t)b * S_ * F_ + h * D_;

    #pragma unroll
    for (int idx = tid; idx < 512; idx += 256) {
        int r = idx >> 4, c = (idx & 15) << 2;
        *(float4*)&Qs[r][c] = *(const float4*)&qbase[(size_t)(q0 + r) * F_ + c];
    }
    __syncthreads();

    int qr = tid >> 3;
    int j0 = (tid & 7) << 2;         // key group for logits
    int d0 = (tid & 7) << 3;         // d group for ctx (8 floats)
    int qg = q0 + qr;
    const float scale = 0.125f;

    float2 st = stats[bh * S_ + qg];
    float mrow = st.x;
    float rs = 1.0f / st.y;

    float O[8];
    #pragma unroll
    for (int i = 0; i < 8; i++) O[i] = 0.f;

    size_t arow = ((size_t)bh * S_ + qg) * S_;

    for (int jb = 0; jb < S_; jb += 32) {
        if (jb <= q0) {
            __syncthreads();
            #pragma unroll
            for (int idx = tid; idx < 512; idx += 256) {
                int r = idx >> 4, c = (idx & 15) << 2;
                *(float4*)&Ks[r][c] = *(const float4*)&kbase[(size_t)(jb + r) * F_ + c];
                *(float4*)&Vs[r][c] = *(const float4*)&vbase[(size_t)(jb + r) * F_ + c];
            }
            __syncthreads();

            float a0 = 0.f, a1 = 0.f, a2 = 0.f, a3 = 0.f;
            #pragma unroll
            for (int kk = 0; kk < 64; kk += 4) {
                float4 qv = *(float4*)&Qs[qr][kk];
                float4 k0v = *(float4*)&Ks[j0 + 0][kk];
                float4 k1v = *(float4*)&Ks[j0 + 1][kk];
                float4 k2v = *(float4*)&Ks[j0 + 2][kk];
                float4 k3v = *(float4*)&Ks[j0 + 3][kk];
                a0 += qv.x*k0v.x + qv.y*k0v.y + qv.z*k0v.z + qv.w*k0v.w;
                a1 += qv.x*k1v.x + qv.y*k1v.y + qv.z*k1v.z + qv.w*k1v.w;
                a2 += qv.x*k2v.x + qv.y*k2v.y + qv.z*k2v.z + qv.w*k2v.w;
                a3 += qv.x*k3v.x + qv.y*k3v.y + qv.z*k3v.z + qv.w*k3v.w;
            }
            float4 p4;
            p4.x = (jb + j0 + 0 <= qg) ? __expf(a0 * scale - mrow) * rs : 0.f;
            p4.y = (jb + j0 + 1 <= qg) ? __expf(a1 * scale - mrow) * rs : 0.f;
            p4.z = (jb + j0 + 2 <= qg) ? __expf(a2 * scale - mrow) * rs : 0.f;
            p4.w = (jb + j0 + 3 <= qg) ? __expf(a3 * scale - mrow) * rs : 0.f;
            *(float4*)&attn[arow + jb + j0] = p4;
            Ps[qr][j0 + 0] = p4.x; Ps[qr][j0 + 1] = p4.y;
            Ps[qr][j0 + 2] = p4.z; Ps[qr][j0 + 3] = p4.w;
            __syncthreads();

            #pragma unroll
            for (int j = 0; j < 32; j++) {
                float pv = Ps[qr][j];
                float4 v0 = *(float4*)&Vs[j][d0];
                float4 v1 = *(float4*)&Vs[j][d0 + 4];
                O[0] += pv * v0.x; O[1] += pv * v0.y; O[2] += pv * v0.z; O[3] += pv * v0.w;
                O[4] += pv * v1.x; O[5] += pv * v1.y; O[6] += pv * v1.z; O[7] += pv * v1.w;
            }
        } else {
            float4 z = make_float4(0.f, 0.f, 0.f, 0.f);
            *(float4*)&attn[arow + jb + j0] = z;
        }
    }

    float* crow = ctx + ((size_t)(b * S_ + qg)) * F_ + h * D_ + d0;
    float4 o0 = make_float4(O[0], O[1], O[2], O[3]);
    float4 o1 = make_float4(O[4], O[5], O[6], O[7]);
    *(float4*)&crow[0] = o0;
    *(float4*)&crow[4] = o1;
}

// ---------------- launch ----------------
extern "C" void kernel_launch(void* const* d_in, const int* in_sizes, int n_in,
                              void* d_out, int out_size) {
    const float* x      = (const float*)d_in[0];
    const float* Wq     = (const float*)d_in[1];
    const float* bq     = (const float*)d_in[2];
    const float* Wk     = (const float*)d_in[3];
    const float* bk     = (const float*)d_in[4];
    const float* Wv     = (const float*)d_in[5];
    const float* bv     = (const float*)d_in[6];
    const float* Wo     = (const float*)d_in[7];
    const float* bo     = (const float*)d_in[8];
    const float* gamma1 = (const float*)d_in[9];
    const float* beta1  = (const float*)d_in[10];
    const float* gamma2 = (const float*)d_in[11];
    const float* beta2  = (const float*)d_in[12];
    const float* pos    = (const float*)d_in[13];

    float* out = (float*)d_out;

    float *xn, *qb, *kb, *vb, *ctx, *tmp, *attn_fb;
    float2* stats;
    cudaGetSymbolAddress((void**)&xn, g_xn);
    cudaGetSymbolAddress((void**)&qb, g_q);
    cudaGetSymbolAddress((void**)&kb, g_k);
    cudaGetSymbolAddress((void**)&vb, g_v);
    cudaGetSymbolAddress((void**)&ctx, g_ctx);
    cudaGetSymbolAddress((void**)&tmp, g_tmp);
    cudaGetSymbolAddress((void**)&stats, g_stats);
    cudaGetSymbolAddress((void**)&attn_fb, g_attn_fallback);

    float* attn = (out_size > OUT_ELEMS) ? (out + OUT_ELEMS) : attn_fb;

    // 1) LN1
    ln_kernel<<<M_, 256>>>(x, gamma1, beta1, xn);

    // 2) Q/K/V projections (pos-emb fused into K epilogue)
    dim3 ggrid(F_ / 64, M_ / 64);
    gemm_kernel<<<ggrid, 256>>>(xn, Wq, bq, nullptr, nullptr, qb);
    gemm_kernel<<<ggrid, 256>>>(xn, Wk, bk, pos,     nullptr, kb);
    gemm_kernel<<<ggrid, 256>>>(xn, Wv, bv, nullptr, nullptr, vb);

    // 3) attention stats (row max / sumexp)
    dim3 agrid(S_ / 32, BH_);
    attn_stats_kernel<<<agrid, 256>>>(qb, kb, stats);

    // 4) probs + ctx
    attn_ctx_kernel<<<agrid, 256>>>(qb, kb, vb, stats, attn, ctx);

    // 5) output projection + residual (xn)
    gemm_kernel<<<ggrid, 256>>>(ctx, Wo, bo, nullptr, xn, tmp);

    // 6) LN2 -> final out
    ln_kernel<<<M_, 256>>>(tmp, gamma2, beta2, out);
}

// round 2
// speedup vs baseline: 4.2711x; 4.2711x over previous
#include <cuda_runtime.h>
#include <math.h>

// Problem constants
#define B_  2
#define S_  2048
#define F_  1024
#define H_  16
#define D_  64
#define M_  (B_ * S_)          // 4096 rows
#define BH_ (B_ * H_)          // 32
#define OUT_ELEMS (M_ * F_)    // 4194304
#define ATTN_ELEMS ((size_t)BH_ * S_ * S_)  // 134217728
#define KBLKS (S_ / 64)        // 32

// ---------------- device scratch (no allocations allowed) ----------------
__device__ float g_xn[OUT_ELEMS];
__device__ float g_q[OUT_ELEMS];
__device__ float g_k[OUT_ELEMS];
__device__ float g_v[OUT_ELEMS];
__device__ float g_ctx[OUT_ELEMS];
__device__ float g_tmp[OUT_ELEMS];
__device__ float g_corrM[(size_t)BH_ * KBLKS * S_];   // running max at write time
__device__ float2 g_finstats[BH_ * S_];               // (m_final, sum_final)
__device__ float g_attn_fallback[ATTN_ELEMS];

// ---------------- LayerNorm: one block per row (1024 cols, 256 thr) ------
__global__ void ln_kernel(const float* __restrict__ x,
                          const float* __restrict__ gamma,
                          const float* __restrict__ beta,
                          float* __restrict__ out) {
    __shared__ float sred[8];
    int row = blockIdx.x;
    int t = threadIdx.x;
    const float4* xr = (const float4*)(x + (size_t)row * F_);
    float4 v = xr[t];

    float s = v.x + v.y + v.z + v.w;
    #pragma unroll
    for (int o = 16; o; o >>= 1) s += __shfl_xor_sync(0xffffffffu, s, o);
    if ((t & 31) == 0) sred[t >> 5] = s;
    __syncthreads();
    float tot = 0.f;
    #pragma unroll
    for (int i = 0; i < 8; i++) tot += sred[i];
    float mean = tot * (1.0f / F_);
    __syncthreads();

    float dx = v.x - mean, dy = v.y - mean, dz = v.z - mean, dw = v.w - mean;
    float ss = dx*dx + dy*dy + dz*dz + dw*dw;
    #pragma unroll
    for (int o = 16; o; o >>= 1) ss += __shfl_xor_sync(0xffffffffu, ss, o);
    if ((t & 31) == 0) sred[t >> 5] = ss;
    __syncthreads();
    float tot2 = 0.f;
    #pragma unroll
    for (int i = 0; i < 8; i++) tot2 += sred[i];
    float rstd = rsqrtf(tot2 * (1.0f / F_) + 1e-6f);

    float4 g4 = ((const float4*)gamma)[t];
    float4 b4 = ((const float4*)beta)[t];
    float4 o4;
    o4.x = dx * rstd * g4.x + b4.x;
    o4.y = dy * rstd * g4.y + b4.y;
    o4.z = dz * rstd * g4.z + b4.z;
    o4.w = dw * rstd * g4.w + b4.w;
    ((float4*)(out + (size_t)row * F_))[t] = o4;
}

// ---------------- GEMM: 128x128 tile, BK=16, 256 threads, 8x8 micro ------
// Thread cols split in two groups (4tx, 64+4tx) for conflict-free Bs reads.
__global__ __launch_bounds__(256, 2)
void gemm_kernel(const float* __restrict__ A,
                 const float* __restrict__ W,
                 const float* __restrict__ bias,
                 const float* __restrict__ pos,   // null or [S_, D_]
                 const float* __restrict__ res,   // null or [M_, F_]
                 float* __restrict__ C) {
    __shared__ float As[16][132];
    __shared__ float Bs[16][128];

    int tid = threadIdx.x;
    int tx = tid & 15;            // 0..15
    int ty = tid >> 4;            // 0..15
    int m0 = blockIdx.y * 128;
    int n0 = blockIdx.x * 128;

    float acc[8][8];
    #pragma unroll
    for (int i = 0; i < 8; i++)
        #pragma unroll
        for (int j = 0; j < 8; j++) acc[i][j] = 0.f;

    for (int k0 = 0; k0 < F_; k0 += 16) {
        // A tile 128x16 -> As[k][m] transposed
        #pragma unroll
        for (int l = 0; l < 2; l++) {
            int f = tid + 256 * l;
            int r = f >> 2, cg = (f & 3) << 2;
            float4 t = *(const float4*)&A[(size_t)(m0 + r) * F_ + k0 + cg];
            As[cg + 0][r] = t.x; As[cg + 1][r] = t.y;
            As[cg + 2][r] = t.z; As[cg + 3][r] = t.w;
        }
        // W tile 16x128
        #pragma unroll
        for (int l = 0; l < 2; l++) {
            int f = tid + 256 * l;
            int r = f >> 5, c4 = (f & 31) << 2;
            *(float4*)&Bs[r][c4] = *(const float4*)&W[(size_t)(k0 + r) * F_ + n0 + c4];
        }
        __syncthreads();

        #pragma unroll
        for (int kk = 0; kk < 16; kk++) {
            float4 a0 = *(float4*)&As[kk][8 * ty];
            float4 a1 = *(float4*)&As[kk][8 * ty + 4];
            float4 b0 = *(float4*)&Bs[kk][4 * tx];
            float4 b1 = *(float4*)&Bs[kk][64 + 4 * tx];
            float av[8] = {a0.x, a0.y, a0.z, a0.w, a1.x, a1.y, a1.z, a1.w};
            float bv[8] = {b0.x, b0.y, b0.z, b0.w, b1.x, b1.y, b1.z, b1.w};
            #pragma unroll
            for (int i = 0; i < 8; i++)
                #pragma unroll
                for (int j = 0; j < 8; j++) acc[i][j] += av[i] * bv[j];
        }
        __syncthreads();
    }

    #pragma unroll
    for (int i = 0; i < 8; i++) {
        int row = m0 + 8 * ty + i;
        int s = row & (S_ - 1);
        #pragma unroll
        for (int g = 0; g < 2; g++) {
            int col0 = n0 + g * 64 + 4 * tx;
            float4 r4;
            float vals[4];
            #pragma unroll
            for (int j = 0; j < 4; j++) {
                int col = col0 + j;
                float val = acc[i][4 * g + j] + bias[col];
                if (pos) val += pos[(size_t)s * D_ + (col & (D_ - 1))];
                if (res) val += res[(size_t)row * F_ + col];
                vals[j] = val;
            }
            r4.x = vals[0]; r4.y = vals[1]; r4.z = vals[2]; r4.w = vals[3];
            *(float4*)&C[(size_t)row * F_ + col0] = r4;
        }
    }
}

// ---------------- Flash attention: 128 q-rows x 64-key tiles -------------
// Writes UNNORMALIZED probs (relative to running max) to attn, the running
// max per (row, keyblock) to corrM, final (max,sum) to finstats, normalized
// ctx to ctx. rescale_kernel fixes attn afterwards.
#define BQ 128
#define BKEY 64
#define QT_ST 132
#define KT_ST 68
#define FLASH_SMEM_FLOATS (64*QT_ST + 64*KT_ST + 64*KT_ST + 128*KT_ST)

__global__ __launch_bounds__(256, 2)
void flash_kernel(const float* __restrict__ q,
                  const float* __restrict__ k,
                  const float* __restrict__ v,
                  float* __restrict__ attn,
                  float* __restrict__ ctx,
                  float* __restrict__ corrM,
                  float2* __restrict__ finstats) {
    extern __shared__ float sm[];
    float* Qt = sm;                          // [64][132] dim-major Q
    float* Kt = Qt + 64 * QT_ST;             // [64][68]  dim-major K
    float* Vs = Kt + 64 * KT_ST;             // [64][68]  key-major V
    float* Ps = Vs + 64 * KT_ST;             // [128][68] row-major P
#define QT(a,b) Qt[(a)*QT_ST+(b)]
#define KT(a,b) Kt[(a)*KT_ST+(b)]
#define VS(a,b) Vs[(a)*KT_ST+(b)]
#define PS(a,b) Ps[(a)*KT_ST+(b)]

    int tid = threadIdx.x;
    int tx = tid & 15, ty = tid >> 4;
    int bh = blockIdx.y;
    int b = bh >> 4, h = bh & 15;
    int q0 = blockIdx.x * BQ;
    const float* qb = q + (size_t)b * S_ * F_ + h * D_;
    const float* kb = k + (size_t)b * S_ * F_ + h * D_;
    const float* vb = v + (size_t)b * S_ * F_ + h * D_;

    // load Q tile transposed: 128 rows x 64 dims
    for (int f = tid; f < 2048; f += 256) {
        int r = f >> 4, cg = (f & 15) << 2;
        float4 t = *(const float4*)&qb[(size_t)(q0 + r) * F_ + cg];
        QT(cg + 0, r) = t.x; QT(cg + 1, r) = t.y;
        QT(cg + 2, r) = t.z; QT(cg + 3, r) = t.w;
    }

    float m[8], l[8], O[8][4];
    #pragma unroll
    for (int i = 0; i < 8; i++) {
        m[i] = -1e30f; l[i] = 0.f;
        O[i][0] = O[i][1] = O[i][2] = O[i][3] = 0.f;
    }
    const float scale = 0.125f;

    for (int jb = 0; jb < q0 + BQ; jb += BKEY) {
        __syncthreads();
        // load K (transposed) and V tiles
        for (int f = tid; f < 1024; f += 256) {
            int r = f >> 4, cg = (f & 15) << 2;
            float4 kt = *(const float4*)&kb[(size_t)(jb + r) * F_ + cg];
            KT(cg + 0, r) = kt.x; KT(cg + 1, r) = kt.y;
            KT(cg + 2, r) = kt.z; KT(cg + 3, r) = kt.w;
            float4 vt = *(const float4*)&vb[(size_t)(jb + r) * F_ + cg];
            *(float4*)&VS(r, cg) = vt;
        }
        __syncthreads();

        // QK^T : Sv[8 rows][4 keys]
        float Sv[8][4];
        #pragma unroll
        for (int i = 0; i < 8; i++)
            Sv[i][0] = Sv[i][1] = Sv[i][2] = Sv[i][3] = 0.f;
        #pragma unroll 8
        for (int kk = 0; kk < 64; kk++) {
            float4 a0 = *(float4*)&QT(kk, 8 * ty);
            float4 a1 = *(float4*)&QT(kk, 8 * ty + 4);
            float4 bv = *(float4*)&KT(kk, 4 * tx);
            float av[8] = {a0.x, a0.y, a0.z, a0.w, a1.x, a1.y, a1.z, a1.w};
            #pragma unroll
            for (int i = 0; i < 8; i++) {
                Sv[i][0] += av[i] * bv.x; Sv[i][1] += av[i] * bv.y;
                Sv[i][2] += av[i] * bv.z; Sv[i][3] += av[i] * bv.w;
            }
        }

        bool needmask = (jb + BKEY - 1 > q0);
        int c0 = jb + 4 * tx;

        #pragma unroll
        for (int i = 0; i < 8; i++) {
            int row = q0 + 8 * ty + i;
            float s0 = Sv[i][0] * scale, s1 = Sv[i][1] * scale;
            float s2 = Sv[i][2] * scale, s3 = Sv[i][3] * scale;
            if (needmask) {
                if (c0 + 0 > row) s0 = -1e30f;
                if (c0 + 1 > row) s1 = -1e30f;
                if (c0 + 2 > row) s2 = -1e30f;
                if (c0 + 3 > row) s3 = -1e30f;
            }
            float mx = fmaxf(fmaxf(s0, s1), fmaxf(s2, s3));
            mx = fmaxf(mx, __shfl_xor_sync(0xffffffffu, mx, 1));
            mx = fmaxf(mx, __shfl_xor_sync(0xffffffffu, mx, 2));
            mx = fmaxf(mx, __shfl_xor_sync(0xffffffffu, mx, 4));
            mx = fmaxf(mx, __shfl_xor_sync(0xffffffffu, mx, 8));
            float mnew = fmaxf(m[i], mx);
            float alpha = __expf(m[i] - mnew);
            float p0 = __expf(s0 - mnew);
            float p1 = __expf(s1 - mnew);
            float p2 = __expf(s2 - mnew);
            float p3 = __expf(s3 - mnew);
            l[i] = l[i] * alpha + (p0 + p1 + p2 + p3);
            O[i][0] *= alpha; O[i][1] *= alpha; O[i][2] *= alpha; O[i][3] *= alpha;
            m[i] = mnew;
            float4 pv = make_float4(p0, p1, p2, p3);
            *(float4*)&attn[((size_t)bh * S_ + row) * S_ + jb + 4 * tx] = pv;
            *(float4*)&PS(8 * ty + i, 4 * tx) = pv;
            if (tx == 0)
                corrM[((size_t)bh * KBLKS + (jb >> 6)) * S_ + row] = mnew;
        }
        __syncthreads();

        // P @ V
        #pragma unroll 4
        for (int j4 = 0; j4 < 64; j4 += 4) {
            float4 v0 = *(float4*)&VS(j4 + 0, 4 * tx);
            float4 v1 = *(float4*)&VS(j4 + 1, 4 * tx);
            float4 v2 = *(float4*)&VS(j4 + 2, 4 * tx);
            float4 v3 = *(float4*)&VS(j4 + 3, 4 * tx);
            #pragma unroll
            for (int i = 0; i < 8; i++) {
                float4 p4 = *(float4*)&PS(8 * ty + i, j4);
                O[i][0] += p4.x * v0.x + p4.y * v1.x + p4.z * v2.x + p4.w * v3.x;
                O[i][1] += p4.x * v0.y + p4.y * v1.y + p4.z * v2.y + p4.w * v3.y;
                O[i][2] += p4.x * v0.z + p4.y * v1.z + p4.z * v2.z + p4.w * v3.z;
                O[i][3] += p4.x * v0.w + p4.y * v1.w + p4.z * v2.w + p4.w * v3.w;
            }
        }
    }

    // finalize: reduce sums across tx, write ctx + stats
    #pragma unroll
    for (int i = 0; i < 8; i++) {
        float ls = l[i];
        ls += __shfl_xor_sync(0xffffffffu, ls, 1);
        ls += __shfl_xor_sync(0xffffffffu, ls, 2);
        ls += __shfl_xor_sync(0xffffffffu, ls, 4);
        ls += __shfl_xor_sync(0xffffffffu, ls, 8);
        float rs = 1.0f / ls;
        int row = q0 + 8 * ty + i;
        float4 o = make_float4(O[i][0] * rs, O[i][1] * rs, O[i][2] * rs, O[i][3] * rs);
        *(float4*)&ctx[((size_t)(b * S_ + row)) * F_ + h * D_ + 4 * tx] = o;
        if (tx == 0) finstats[bh * S_ + row] = make_float2(m[i], ls);
    }
}

// ---------------- rescale: normalize attn, zero-fill masked region -------
__global__ void rescale_kernel(float* __restrict__ attn,
                               const float* __restrict__ corrM,
                               const float2* __restrict__ finstats) {
    size_t stride = (size_t)gridDim.x * blockDim.x;
    const size_t total = ATTN_ELEMS / 4;
    for (size_t f = (size_t)blockIdx.x * blockDim.x + threadIdx.x; f < total; f += stride) {
        int col4 = (int)(f & (S_ / 4 - 1));
        int row  = (int)((f >> 9) & (S_ - 1));
        int bh   = (int)(f >> 20);
        int col0 = col4 << 2;
        float4* p = (float4*)attn + f;
        if (col0 > row) {
            *p = make_float4(0.f, 0.f, 0.f, 0.f);
        } else {
            float2 st = finstats[bh * S_ + row];
            float mw = corrM[((size_t)bh * KBLKS + (col0 >> 6)) * S_ + row];
            float c = __expf(mw - st.x) / st.y;
            float4 vv = *p;
            vv.x *= c; vv.y *= c; vv.z *= c; vv.w *= c;
            *p = vv;
        }
    }
}

// ---------------- launch ----------------
extern "C" void kernel_launch(void* const* d_in, const int* in_sizes, int n_in,
                              void* d_out, int out_size) {
    const float* x      = (const float*)d_in[0];
    const float* Wq     = (const float*)d_in[1];
    const float* bq     = (const float*)d_in[2];
    const float* Wk     = (const float*)d_in[3];
    const float* bk     = (const float*)d_in[4];
    const float* Wv     = (const float*)d_in[5];
    const float* bv     = (const float*)d_in[6];
    const float* Wo     = (const float*)d_in[7];
    const float* bo     = (const float*)d_in[8];
    const float* gamma1 = (const float*)d_in[9];
    const float* beta1  = (const float*)d_in[10];
    const float* gamma2 = (const float*)d_in[11];
    const float* beta2  = (const float*)d_in[12];
    const float* pos    = (const float*)d_in[13];

    float* out = (float*)d_out;

    float *xn, *qb, *kb, *vb, *ctx, *tmp, *corrM, *attn_fb;
    float2* finstats;
    cudaGetSymbolAddress((void**)&xn, g_xn);
    cudaGetSymbolAddress((void**)&qb, g_q);
    cudaGetSymbolAddress((void**)&kb, g_k);
    cudaGetSymbolAddress((void**)&vb, g_v);
    cudaGetSymbolAddress((void**)&ctx, g_ctx);
    cudaGetSymbolAddress((void**)&tmp, g_tmp);
    cudaGetSymbolAddress((void**)&corrM, g_corrM);
    cudaGetSymbolAddress((void**)&finstats, g_finstats);
    cudaGetSymbolAddress((void**)&attn_fb, g_attn_fallback);

    float* attn = (out_size > OUT_ELEMS) ? (out + OUT_ELEMS) : attn_fb;

    static bool attr_set = false;
    if (!attr_set) {
        cudaFuncSetAttribute(flash_kernel,
                             cudaFuncAttributeMaxDynamicSharedMemorySize,
                             FLASH_SMEM_FLOATS * 4);
        attr_set = true;
    }

    // 1) LN1
    ln_kernel<<<M_, 256>>>(x, gamma1, beta1, xn);

    // 2) Q/K/V projections (pos-emb fused into K epilogue)
    dim3 ggrid(F_ / 128, M_ / 128);
    gemm_kernel<<<ggrid, 256>>>(xn, Wq, bq, nullptr, nullptr, qb);
    gemm_kernel<<<ggrid, 256>>>(xn, Wk, bk, pos,     nullptr, kb);
    gemm_kernel<<<ggrid, 256>>>(xn, Wv, bv, nullptr, nullptr, vb);

    // 3) fused flash attention (ctx + unnormalized attn + stats)
    dim3 fgrid(S_ / BQ, BH_);
    flash_kernel<<<fgrid, 256, FLASH_SMEM_FLOATS * 4>>>(qb, kb, vb, attn, ctx,
                                                        corrM, finstats);

    // 4) normalize attn + zero-fill masked triangle
    rescale_kernel<<<32768, 256>>>(attn, corrM, finstats);

    // 5) output projection + residual (xn)
    gemm_kernel<<<ggrid, 256>>>(ctx, Wo, bo, nullptr, xn, tmp);

    // 6) LN2 -> final out
    ln_kernel<<<M_, 256>>>(tmp, gamma2, beta2, out);
}

// round 5
// speedup vs baseline: 5.5873x; 1.3082x over previous
#include <cuda_runtime.h>
#include <cuda_bf16.h>
#include <cstdint>
#include <math.h>

// Problem constants
#define B_  2
#define S_  2048
#define F_  1024
#define H_  16
#define D_  64
#define M_  (B_ * S_)          // 4096 rows
#define BH_ (B_ * H_)          // 32
#define OUT_ELEMS (M_ * F_)    // 4194304
#define ATTN_ELEMS ((size_t)BH_ * S_ * S_)  // 134217728
#define KBLKS (S_ / 64)        // 32

// ---------------- device scratch (no allocations allowed) ----------------
__device__ float g_xn[OUT_ELEMS];
__device__ float g_q[OUT_ELEMS];
__device__ float g_k[OUT_ELEMS];
__device__ float g_v[OUT_ELEMS];
__device__ float g_ctx[OUT_ELEMS];
__device__ float g_tmp[OUT_ELEMS];
__device__ float g_corrM[(size_t)BH_ * KBLKS * S_];
__device__ float2 g_finstats[BH_ * S_];
__device__ float g_attn_fallback[ATTN_ELEMS];

// bf16 split buffers
__device__ __nv_bfloat16 g_xn_hi[OUT_ELEMS];
__device__ __nv_bfloat16 g_xn_lo[OUT_ELEMS];
__device__ __nv_bfloat16 g_ctx_hi[OUT_ELEMS];
__device__ __nv_bfloat16 g_ctx_lo[OUT_ELEMS];
__device__ __nv_bfloat16 g_WqT_hi[F_ * F_];
__device__ __nv_bfloat16 g_WqT_lo[F_ * F_];
__device__ __nv_bfloat16 g_WkT_hi[F_ * F_];
__device__ __nv_bfloat16 g_WkT_lo[F_ * F_];
__device__ __nv_bfloat16 g_WvT_hi[F_ * F_];
__device__ __nv_bfloat16 g_WvT_lo[F_ * F_];
__device__ __nv_bfloat16 g_WoT_hi[F_ * F_];
__device__ __nv_bfloat16 g_WoT_lo[F_ * F_];

// ---------------- helpers ----------------
__device__ __forceinline__ uint32_t smem_u32(const void* p) {
    uint32_t a;
    asm("{ .reg .u64 t; cvta.to.shared.u64 t, %1; cvt.u32.u64 %0, t; }"
        : "=r"(a) : "l"(p));
    return a;
}

__device__ __forceinline__ void ldsm4(uint32_t* r, uint32_t addr) {
    asm volatile("ldmatrix.sync.aligned.m8n8.x4.shared.b16 {%0,%1,%2,%3}, [%4];"
                 : "=r"(r[0]), "=r"(r[1]), "=r"(r[2]), "=r"(r[3]) : "r"(addr));
}

__device__ __forceinline__ void mma_bf16(float* c, const uint32_t* a,
                                         uint32_t b0, uint32_t b1) {
    asm volatile("mma.sync.aligned.m16n8k16.row.col.f32.bf16.bf16.f32 "
                 "{%0,%1,%2,%3}, {%4,%5,%6,%7}, {%8,%9}, {%0,%1,%2,%3};"
                 : "+f"(c[0]), "+f"(c[1]), "+f"(c[2]), "+f"(c[3])
                 : "r"(a[0]), "r"(a[1]), "r"(a[2]), "r"(a[3]), "r"(b0), "r"(b1));
}

__device__ __forceinline__ void split_f32(float a, __nv_bfloat16& hi, __nv_bfloat16& lo) {
    hi = __float2bfloat16(a);
    lo = __float2bfloat16(a - __bfloat162float(hi));
}

// ---------------- LayerNorm ----------------
__global__ void ln_kernel(const float* __restrict__ x,
                          const float* __restrict__ gamma,
                          const float* __restrict__ beta,
                          float* __restrict__ out) {
    __shared__ float sred[8];
    int row = blockIdx.x;
    int t = threadIdx.x;
    const float4* xr = (const float4*)(x + (size_t)row * F_);
    float4 v = xr[t];

    float s = v.x + v.y + v.z + v.w;
    #pragma unroll
    for (int o = 16; o; o >>= 1) s += __shfl_xor_sync(0xffffffffu, s, o);
    if ((t & 31) == 0) sred[t >> 5] = s;
    __syncthreads();
    float tot = 0.f;
    #pragma unroll
    for (int i = 0; i < 8; i++) tot += sred[i];
    float mean = tot * (1.0f / F_);
    __syncthreads();

    float dx = v.x - mean, dy = v.y - mean, dz = v.z - mean, dw = v.w - mean;
    float ss = dx*dx + dy*dy + dz*dz + dw*dw;
    #pragma unroll
    for (int o = 16; o; o >>= 1) ss += __shfl_xor_sync(0xffffffffu, ss, o);
    if ((t & 31) == 0) sred[t >> 5] = ss;
    __syncthreads();
    float tot2 = 0.f;
    #pragma unroll
    for (int i = 0; i < 8; i++) tot2 += sred[i];
    float rstd = rsqrtf(tot2 * (1.0f / F_) + 1e-6f);

    float4 g4 = ((const float4*)gamma)[t];
    float4 b4 = ((const float4*)beta)[t];
    float4 o4;
    o4.x = dx * rstd * g4.x + b4.x;
    o4.y = dy * rstd * g4.y + b4.y;
    o4.z = dz * rstd * g4.z + b4.z;
    o4.w = dw * rstd * g4.w + b4.w;
    ((float4*)(out + (size_t)row * F_))[t] = o4;
}

// ---------------- split fp32 -> bf16 hi/lo ----------------
__global__ void split_kernel(const float* __restrict__ in,
                             __nv_bfloat16* __restrict__ hi,
                             __nv_bfloat16* __restrict__ lo, int n4) {
    int idx = blockIdx.x * blockDim.x + threadIdx.x;
    if (idx >= n4) return;
    float4 v = ((const float4*)in)[idx];
    __nv_bfloat16 h[4], l[4];
    split_f32(v.x, h[0], l[0]); split_f32(v.y, h[1], l[1]);
    split_f32(v.z, h[2], l[2]); split_f32(v.w, h[3], l[3]);
    __nv_bfloat162* hp = (__nv_bfloat162*)hi;
    __nv_bfloat162* lp = (__nv_bfloat162*)lo;
    hp[idx * 2 + 0] = __nv_bfloat162(h[0], h[1]);
    hp[idx * 2 + 1] = __nv_bfloat162(h[2], h[3]);
    lp[idx * 2 + 0] = __nv_bfloat162(l[0], l[1]);
    lp[idx * 2 + 1] = __nv_bfloat162(l[2], l[3]);
}

// ---------------- transpose + split: W[k][n] -> T[n][k] bf16 hi/lo -------
__global__ void transpose_split_kernel(const float* __restrict__ W,
                                       __nv_bfloat16* __restrict__ hiT,
                                       __nv_bfloat16* __restrict__ loT) {
    __shared__ float t[32][33];
    int bx = blockIdx.x * 32;  // n
    int by = blockIdx.y * 32;  // k
    int tx = threadIdx.x, ty = threadIdx.y;
    #pragma unroll
    for (int i = 0; i < 4; i++)
        t[ty + 8 * i][tx] = W[(size_t)(by + ty + 8 * i) * F_ + bx + tx];
    __syncthreads();
    #pragma unroll
    for (int i = 0; i < 4; i++) {
        float v = t[tx][ty + 8 * i];
        __nv_bfloat16 h, l;
        split_f32(v, h, l);
        size_t o = (size_t)(bx + ty + 8 * i) * F_ + by + tx;
        hiT[o] = h;
        loT[o] = l;
    }
}

// ---------------- mma.sync GEMM: C = A @ W (+bias)(+pos)(+res) -----------
// 128x128 tile, BK=32, 8 warps in 4(m) x 2(n). bf16 3-product split.
#define GBK 32
#define KPAD 40   // k-stride in bf16 elems (80B rows: ldmatrix conflict-free)

__global__ __launch_bounds__(256, 2)
void gemm_mma(const __nv_bfloat16* __restrict__ Ahi,
              const __nv_bfloat16* __restrict__ Alo,
              const __nv_bfloat16* __restrict__ BhiT,
              const __nv_bfloat16* __restrict__ BloT,
              const float* __restrict__ bias,
              const float* __restrict__ pos,   // null or [S_, D_]
              const float* __restrict__ res,   // null or [M_, F_]
              float* __restrict__ C) {
    __shared__ __nv_bfloat16 sAhi[128][KPAD];
    __shared__ __nv_bfloat16 sAlo[128][KPAD];
    __shared__ __nv_bfloat16 sBhi[128][KPAD];
    __shared__ __nv_bfloat16 sBlo[128][KPAD];

    int tid = threadIdx.x;
    int warp = tid >> 5, lane = tid & 31;
    int m0 = blockIdx.y * 128;
    int n0 = blockIdx.x * 128;
    int mw = (warp >> 1) * 32;   // warp m offset within tile
    int nw = (warp & 1) * 64;    // warp n offset within tile

    float acc[2][8][4];
    #pragma unroll
    for (int i = 0; i < 2; i++)
        #pragma unroll
        for (int j = 0; j < 8; j++)
            #pragma unroll
            for (int c = 0; c < 4; c++) acc[i][j][c] = 0.f;

    // ldmatrix lane address components
    int a_row = (lane & 15);                 // + mw + 16*mi
    int a_col = (lane & 16) >> 1;            // 0 or 8
    int b_row = (lane & 7) + ((lane & 16) >> 1);  // + nw + 16*ni
    int b_col = (lane & 8);                  // 0 or 8

    for (int kc = 0; kc < F_; kc += GBK) {
        // load 4 tiles of 128x32 bf16; each thread 2 x uint4 per tile
        #pragma unroll
        for (int i = 0; i < 2; i++) {
            int f = tid + 256 * i;
            int r = f >> 2, g = f & 3;
            size_t asrc = (size_t)(m0 + r) * F_ + kc + g * 8;
            size_t bsrc = (size_t)(n0 + r) * F_ + kc + g * 8;
            *(uint4*)&sAhi[r][g * 8] = *(const uint4*)(Ahi + asrc);
            *(uint4*)&sAlo[r][g * 8] = *(const uint4*)(Alo + asrc);
            *(uint4*)&sBhi[r][g * 8] = *(const uint4*)(BhiT + bsrc);
            *(uint4*)&sBlo[r][g * 8] = *(const uint4*)(BloT + bsrc);
        }
        __syncthreads();

        #pragma unroll
        for (int ks = 0; ks < 2; ks++) {
            int k0 = ks * 16;
            uint32_t ah[2][4], al[2][4];
            #pragma unroll
            for (int mi = 0; mi < 2; mi++) {
                ldsm4(ah[mi], smem_u32(&sAhi[mw + 16 * mi + a_row][k0 + a_col]));
                ldsm4(al[mi], smem_u32(&sAlo[mw + 16 * mi + a_row][k0 + a_col]));
            }
            #pragma unroll
            for (int ni = 0; ni < 4; ni++) {
                uint32_t bh[4], bl[4];
                ldsm4(bh, smem_u32(&sBhi[nw + 16 * ni + b_row][k0 + b_col]));
                ldsm4(bl, smem_u32(&sBlo[nw + 16 * ni + b_row][k0 + b_col]));
                #pragma unroll
                for (int mi = 0; mi < 2; mi++) {
                    mma_bf16(acc[mi][2 * ni + 0], ah[mi], bh[0], bh[1]);
                    mma_bf16(acc[mi][2 * ni + 0], al[mi], bh[0], bh[1]);
                    mma_bf16(acc[mi][2 * ni + 0], ah[mi], bl[0], bl[1]);
                    mma_bf16(acc[mi][2 * ni + 1], ah[mi], bh[2], bh[3]);
                    mma_bf16(acc[mi][2 * ni + 1], al[mi], bh[2], bh[3]);
                    mma_bf16(acc[mi][2 * ni + 1], ah[mi], bl[2], bl[3]);
                }
            }
        }
        __syncthreads();
    }

    // epilogue: c0,c1 -> row gid; c2,c3 -> row gid+8
    int gid = lane >> 2, tig = lane & 3;
    #pragma unroll
    for (int mi = 0; mi < 2; mi++) {
        #pragma unroll
        for (int nj = 0; nj < 8; nj++) {
            int row = m0 + mw + 16 * mi + gid;
            int col = n0 + nw + 8 * nj + 2 * tig;
            #pragma unroll
            for (int half = 0; half < 2; half++) {
                int r = row + half * 8;
                int s = r & (S_ - 1);
                float v0 = acc[mi][nj][half * 2 + 0] + bias[col];
                float v1 = acc[mi][nj][half * 2 + 1] + bias[col + 1];
                if (pos) {
                    v0 += pos[(size_t)s * D_ + (col & (D_ - 1))];
                    v1 += pos[(size_t)s * D_ + ((col + 1) & (D_ - 1))];
                }
                if (res) {
                    v0 += res[(size_t)r * F_ + col];
                    v1 += res[(size_t)r * F_ + col + 1];
                }
                *(float2*)&C[(size_t)r * F_ + col] = make_float2(v0, v1);
            }
        }
    }
}

// ---------------- Flash attention (unchanged from R1) --------------------
#define BQ 128
#define BKEY 64
#define QT_ST 132
#define KT_ST 68
#define FLASH_SMEM_FLOATS (64*QT_ST + 64*KT_ST + 64*KT_ST + 128*KT_ST)

__global__ __launch_bounds__(256, 2)
void flash_kernel(const float* __restrict__ q,
                  const float* __restrict__ k,
                  const float* __restrict__ v,
                  float* __restrict__ attn,
                  float* __restrict__ ctx,
                  float* __restrict__ corrM,
                  float2* __restrict__ finstats) {
    extern __shared__ float smf[];
    float* Qt = smf;
    float* Kt = Qt + 64 * QT_ST;
    float* Vs = Kt + 64 * KT_ST;
    float* Ps = Vs + 64 * KT_ST;
#define QT(a,b) Qt[(a)*QT_ST+(b)]
#define KT(a,b) Kt[(a)*KT_ST+(b)]
#define VS(a,b) Vs[(a)*KT_ST+(b)]
#define PS(a,b) Ps[(a)*KT_ST+(b)]

    int tid = threadIdx.x;
    int tx = tid & 15, ty = tid >> 4;
    int bh = blockIdx.y;
    int b = bh >> 4, h = bh & 15;
    int q0 = blockIdx.x * BQ;
    const float* qb = q + (size_t)b * S_ * F_ + h * D_;
    const float* kb = k + (size_t)b * S_ * F_ + h * D_;
    const float* vb = v + (size_t)b * S_ * F_ + h * D_;

    for (int f = tid; f < 2048; f += 256) {
        int r = f >> 4, cg = (f & 15) << 2;
        float4 t = *(const float4*)&qb[(size_t)(q0 + r) * F_ + cg];
        QT(cg + 0, r) = t.x; QT(cg + 1, r) = t.y;
        QT(cg + 2, r) = t.z; QT(cg + 3, r) = t.w;
    }

    float m[8], l[8], O[8][4];
    #pragma unroll
    for (int i = 0; i < 8; i++) {
        m[i] = -1e30f; l[i] = 0.f;
        O[i][0] = O[i][1] = O[i][2] = O[i][3] = 0.f;
    }
    const float scale = 0.125f;

    for (int jb = 0; jb < q0 + BQ; jb += BKEY) {
        __syncthreads();
        for (int f = tid; f < 1024; f += 256) {
            int r = f >> 4, cg = (f & 15) << 2;
            float4 kt = *(const float4*)&kb[(size_t)(jb + r) * F_ + cg];
            KT(cg + 0, r) = kt.x; KT(cg + 1, r) = kt.y;
            KT(cg + 2, r) = kt.z; KT(cg + 3, r) = kt.w;
            float4 vt = *(const float4*)&vb[(size_t)(jb + r) * F_ + cg];
            *(float4*)&VS(r, cg) = vt;
        }
        __syncthreads();

        float Sv[8][4];
        #pragma unroll
        for (int i = 0; i < 8; i++)
            Sv[i][0] = Sv[i][1] = Sv[i][2] = Sv[i][3] = 0.f;
        #pragma unroll 8
        for (int kk = 0; kk < 64; kk++) {
            float4 a0 = *(float4*)&QT(kk, 8 * ty);
            float4 a1 = *(float4*)&QT(kk, 8 * ty + 4);
            float4 bv = *(float4*)&KT(kk, 4 * tx);
            float av[8] = {a0.x, a0.y, a0.z, a0.w, a1.x, a1.y, a1.z, a1.w};
            #pragma unroll
            for (int i = 0; i < 8; i++) {
                Sv[i][0] += av[i] * bv.x; Sv[i][1] += av[i] * bv.y;
                Sv[i][2] += av[i] * bv.z; Sv[i][3] += av[i] * bv.w;
            }
        }

        bool needmask = (jb + BKEY - 1 > q0);
        int c0 = jb + 4 * tx;

        #pragma unroll
        for (int i = 0; i < 8; i++) {
            int row = q0 + 8 * ty + i;
            float s0 = Sv[i][0] * scale, s1 = Sv[i][1] * scale;
            float s2 = Sv[i][2] * scale, s3 = Sv[i][3] * scale;
            if (needmask) {
                if (c0 + 0 > row) s0 = -1e30f;
                if (c0 + 1 > row) s1 = -1e30f;
                if (c0 + 2 > row) s2 = -1e30f;
                if (c0 + 3 > row) s3 = -1e30f;
            }
            float mx = fmaxf(fmaxf(s0, s1), fmaxf(s2, s3));
            mx = fmaxf(mx, __shfl_xor_sync(0xffffffffu, mx, 1));
            mx = fmaxf(mx, __shfl_xor_sync(0xffffffffu, mx, 2));
            mx = fmaxf(mx, __shfl_xor_sync(0xffffffffu, mx, 4));
            mx = fmaxf(mx, __shfl_xor_sync(0xffffffffu, mx, 8));
            float mnew = fmaxf(m[i], mx);
            float alpha = __expf(m[i] - mnew);
            float p0 = __expf(s0 - mnew);
            float p1 = __expf(s1 - mnew);
            float p2 = __expf(s2 - mnew);
            float p3 = __expf(s3 - mnew);
            l[i] = l[i] * alpha + (p0 + p1 + p2 + p3);
            O[i][0] *= alpha; O[i][1] *= alpha; O[i][2] *= alpha; O[i][3] *= alpha;
            m[i] = mnew;
            float4 pv = make_float4(p0, p1, p2, p3);
            *(float4*)&attn[((size_t)bh * S_ + row) * S_ + jb + 4 * tx] = pv;
            *(float4*)&PS(8 * ty + i, 4 * tx) = pv;
            if (tx == 0)
                corrM[((size_t)bh * KBLKS + (jb >> 6)) * S_ + row] = mnew;
        }
        __syncthreads();

        #pragma unroll 4
        for (int j4 = 0; j4 < 64; j4 += 4) {
            float4 v0 = *(float4*)&VS(j4 + 0, 4 * tx);
            float4 v1 = *(float4*)&VS(j4 + 1, 4 * tx);
            float4 v2 = *(float4*)&VS(j4 + 2, 4 * tx);
            float4 v3 = *(float4*)&VS(j4 + 3, 4 * tx);
            #pragma unroll
            for (int i = 0; i < 8; i++) {
                float4 p4 = *(float4*)&PS(8 * ty + i, j4);
                O[i][0] += p4.x * v0.x + p4.y * v1.x + p4.z * v2.x + p4.w * v3.x;
                O[i][1] += p4.x * v0.y + p4.y * v1.y + p4.z * v2.y + p4.w * v3.y;
                O[i][2] += p4.x * v0.z + p4.y * v1.z + p4.z * v2.z + p4.w * v3.z;
                O[i][3] += p4.x * v0.w + p4.y * v1.w + p4.z * v2.w + p4.w * v3.w;
            }
        }
    }

    #pragma unroll
    for (int i = 0; i < 8; i++) {
        float ls = l[i];
        ls += __shfl_xor_sync(0xffffffffu, ls, 1);
        ls += __shfl_xor_sync(0xffffffffu, ls, 2);
        ls += __shfl_xor_sync(0xffffffffu, ls, 4);
        ls += __shfl_xor_sync(0xffffffffu, ls, 8);
        float rs = 1.0f / ls;
        int row = q0 + 8 * ty + i;
        float4 o = make_float4(O[i][0] * rs, O[i][1] * rs, O[i][2] * rs, O[i][3] * rs);
        *(float4*)&ctx[((size_t)(b * S_ + row)) * F_ + h * D_ + 4 * tx] = o;
        if (tx == 0) finstats[bh * S_ + row] = make_float2(m[i], ls);
    }
}

// ---------------- rescale ----------------
__global__ void rescale_kernel(float* __restrict__ attn,
                               const float* __restrict__ corrM,
                               const float2* __restrict__ finstats) {
    size_t stride = (size_t)gridDim.x * blockDim.x;
    const size_t total = ATTN_ELEMS / 4;
    for (size_t f = (size_t)blockIdx.x * blockDim.x + threadIdx.x; f < total; f += stride) {
        int col4 = (int)(f & (S_ / 4 - 1));
        int row  = (int)((f >> 9) & (S_ - 1));
        int bh   = (int)(f >> 20);
        int col0 = col4 << 2;
        float4* p = (float4*)attn + f;
        if (col0 > row) {
            *p = make_float4(0.f, 0.f, 0.f, 0.f);
        } else {
            float2 st = finstats[bh * S_ + row];
            float mw = corrM[((size_t)bh * KBLKS + (col0 >> 6)) * S_ + row];
            float c = __expf(mw - st.x) / st.y;
            float4 vv = *p;
            vv.x *= c; vv.y *= c; vv.z *= c; vv.w *= c;
            *p = vv;
        }
    }
}

// ---------------- launch ----------------
extern "C" void kernel_launch(void* const* d_in, const int* in_sizes, int n_in,
                              void* d_out, int out_size) {
    const float* x      = (const float*)d_in[0];
    const float* Wq     = (const float*)d_in[1];
    const float* bq     = (const float*)d_in[2];
    const float* Wk     = (const float*)d_in[3];
    const float* bk     = (const float*)d_in[4];
    const float* Wv     = (const float*)d_in[5];
    const float* bv     = (const float*)d_in[6];
    const float* Wo     = (const float*)d_in[7];
    const float* bo     = (const float*)d_in[8];
    const float* gamma1 = (const float*)d_in[9];
    const float* beta1  = (const float*)d_in[10];
    const float* gamma2 = (const float*)d_in[11];
    const float* beta2  = (const float*)d_in[12];
    const float* pos    = (const float*)d_in[13];

    float* out = (float*)d_out;

    float *xn, *qb, *kb, *vb, *ctx, *tmp, *corrM, *attn_fb;
    float2* finstats;
    cudaGetSymbolAddress((void**)&xn, g_xn);
    cudaGetSymbolAddress((void**)&qb, g_q);
    cudaGetSymbolAddress((void**)&kb, g_k);
    cudaGetSymbolAddress((void**)&vb, g_v);
    cudaGetSymbolAddress((void**)&ctx, g_ctx);
    cudaGetSymbolAddress((void**)&tmp, g_tmp);
    cudaGetSymbolAddress((void**)&corrM, g_corrM);
    cudaGetSymbolAddress((void**)&finstats, g_finstats);
    cudaGetSymbolAddress((void**)&attn_fb, g_attn_fallback);

    __nv_bfloat16 *xnh, *xnl, *ctxh, *ctxl;
    __nv_bfloat16 *wqh, *wql, *wkh, *wkl, *wvh, *wvl, *woh, *wol;
    cudaGetSymbolAddress((void**)&xnh, g_xn_hi);
    cudaGetSymbolAddress((void**)&xnl, g_xn_lo);
    cudaGetSymbolAddress((void**)&ctxh, g_ctx_hi);
    cudaGetSymbolAddress((void**)&ctxl, g_ctx_lo);
    cudaGetSymbolAddress((void**)&wqh, g_WqT_hi);
    cudaGetSymbolAddress((void**)&wql, g_WqT_lo);
    cudaGetSymbolAddress((void**)&wkh, g_WkT_hi);
    cudaGetSymbolAddress((void**)&wkl, g_WkT_lo);
    cudaGetSymbolAddress((void**)&wvh, g_WvT_hi);
    cudaGetSymbolAddress((void**)&wvl, g_WvT_lo);
    cudaGetSymbolAddress((void**)&woh, g_WoT_hi);
    cudaGetSymbolAddress((void**)&wol, g_WoT_lo);

    float* attn = (out_size > OUT_ELEMS) ? (out + OUT_ELEMS) : attn_fb;

    cudaFuncSetAttribute(flash_kernel,
                         cudaFuncAttributeMaxDynamicSharedMemorySize,
                         FLASH_SMEM_FLOATS * 4);

    // 1) LN1 + splits + weight transpose-splits
    ln_kernel<<<M_, 256>>>(x, gamma1, beta1, xn);
    split_kernel<<<OUT_ELEMS / 4 / 256, 256>>>(xn, xnh, xnl, OUT_ELEMS / 4);
    dim3 tb(32, 8), tg(F_ / 32, F_ / 32);
    transpose_split_kernel<<<tg, tb>>>(Wq, wqh, wql);
    transpose_split_kernel<<<tg, tb>>>(Wk, wkh, wkl);
    transpose_split_kernel<<<tg, tb>>>(Wv, wvh, wvl);
    transpose_split_kernel<<<tg, tb>>>(Wo, woh, wol);

    // 2) Q/K/V projections on tensor cores (mma.sync)
    dim3 ggrid(F_ / 128, M_ / 128);
    gemm_mma<<<ggrid, 256>>>(xnh, xnl, wqh, wql, bq, nullptr, nullptr, qb);
    gemm_mma<<<ggrid, 256>>>(xnh, xnl, wkh, wkl, bk, pos,     nullptr, kb);
    gemm_mma<<<ggrid, 256>>>(xnh, xnl, wvh, wvl, bv, nullptr, nullptr, vb);

    // 3) flash attention
    dim3 fgrid(S_ / BQ, BH_);
    flash_kernel<<<fgrid, 256, FLASH_SMEM_FLOATS * 4>>>(qb, kb, vb, attn, ctx,
                                                        corrM, finstats);

    // 4) normalize attn + zero-fill masked triangle
    rescale_kernel<<<32768, 256>>>(attn, corrM, finstats);

    // 5) output projection + residual (mma.sync)
    split_kernel<<<OUT_ELEMS / 4 / 256, 256>>>(ctx, ctxh, ctxl, OUT_ELEMS / 4);
    gemm_mma<<<ggrid, 256>>>(ctxh, ctxl, woh, wol, bo, nullptr, xn, tmp);

    // 6) LN2
    ln_kernel<<<M_, 256>>>(tmp, gamma2, beta2, out);
}

// round 6
// speedup vs baseline: 7.4285x; 1.3295x over previous
#include <cuda_runtime.h>
#include <cuda_bf16.h>
#include <cstdint>
#include <math.h>

// Problem constants
#define B_  2
#define S_  2048
#define F_  1024
#define H_  16
#define D_  64
#define M_  (B_ * S_)          // 4096 rows
#define BH_ (B_ * H_)          // 32
#define OUT_ELEMS (M_ * F_)    // 4194304
#define ATTN_ELEMS ((size_t)BH_ * S_ * S_)  // 134217728

// ---------------- device scratch (no allocations allowed) ----------------
__device__ float g_xn[OUT_ELEMS];
__device__ float g_tmp[OUT_ELEMS];
__device__ float g_rs[BH_ * S_];
__device__ float g_attn_fallback[ATTN_ELEMS];

__device__ __nv_bfloat16 g_xn_hi[OUT_ELEMS];
__device__ __nv_bfloat16 g_xn_lo[OUT_ELEMS];
__device__ __nv_bfloat16 g_qh[OUT_ELEMS];
__device__ __nv_bfloat16 g_ql[OUT_ELEMS];
__device__ __nv_bfloat16 g_kh[OUT_ELEMS];
__device__ __nv_bfloat16 g_kl[OUT_ELEMS];
__device__ __nv_bfloat16 g_vh[OUT_ELEMS];
__device__ __nv_bfloat16 g_vl[OUT_ELEMS];
__device__ __nv_bfloat16 g_ctx_hi[OUT_ELEMS];
__device__ __nv_bfloat16 g_ctx_lo[OUT_ELEMS];
__device__ __nv_bfloat16 g_WqT_hi[F_ * F_];
__device__ __nv_bfloat16 g_WqT_lo[F_ * F_];
__device__ __nv_bfloat16 g_WkT_hi[F_ * F_];
__device__ __nv_bfloat16 g_WkT_lo[F_ * F_];
__device__ __nv_bfloat16 g_WvT_hi[F_ * F_];
__device__ __nv_bfloat16 g_WvT_lo[F_ * F_];
__device__ __nv_bfloat16 g_WoT_hi[F_ * F_];
__device__ __nv_bfloat16 g_WoT_lo[F_ * F_];

// ---------------- helpers ----------------
__device__ __forceinline__ uint32_t smem_u32(const void* p) {
    uint32_t a;
    asm("{ .reg .u64 t; cvta.to.shared.u64 t, %1; cvt.u32.u64 %0, t; }"
        : "=r"(a) : "l"(p));
    return a;
}
__device__ __forceinline__ void ldsm4(uint32_t* r, uint32_t addr) {
    asm volatile("ldmatrix.sync.aligned.m8n8.x4.shared.b16 {%0,%1,%2,%3}, [%4];"
                 : "=r"(r[0]), "=r"(r[1]), "=r"(r[2]), "=r"(r[3]) : "r"(addr));
}
__device__ __forceinline__ void mma_bf16(float* c, const uint32_t* a,
                                         uint32_t b0, uint32_t b1) {
    asm volatile("mma.sync.aligned.m16n8k16.row.col.f32.bf16.bf16.f32 "
                 "{%0,%1,%2,%3}, {%4,%5,%6,%7}, {%8,%9}, {%0,%1,%2,%3};"
                 : "+f"(c[0]), "+f"(c[1]), "+f"(c[2]), "+f"(c[3])
                 : "r"(a[0]), "r"(a[1]), "r"(a[2]), "r"(a[3]), "r"(b0), "r"(b1));
}
__device__ __forceinline__ void split_f32(float a, __nv_bfloat16& hi, __nv_bfloat16& lo) {
    hi = __float2bfloat16(a);
    lo = __float2bfloat16(a - __bfloat162float(hi));
}
// exp(s*0.125) via FMA-pipe exp2 (no MUFU). s is the raw dot product.
#define EXP_C1 0.18033688011112042f   // 0.125 * log2(e)
__device__ __forceinline__ float fexp_dot(float dot) {
    float y = dot * EXP_C1;
    y = fminf(fmaxf(y, -126.f), 126.f);
    float t = y + 12582912.f;
    int e = (__float_as_int(t) - 0x4B400000) << 23;
    float f = y - (t - 12582912.f);
    float p = 0.00133335581f;
    p = fmaf(p, f, 0.00961812910f);
    p = fmaf(p, f, 0.0555041086f);
    p = fmaf(p, f, 0.240226507f);
    p = fmaf(p, f, 0.693147182f);
    p = fmaf(p, f, 1.0f);
    return __int_as_float(__float_as_int(p) + e);
}
// pack two f32 -> bf16x2 reg, return residuals
__device__ __forceinline__ uint32_t pack_hi(float a, float b, float& ra, float& rb) {
    __nv_bfloat162 h = __floats2bfloat162_rn(a, b);
    ra = a - __bfloat162float(h.x);
    rb = b - __bfloat162float(h.y);
    return *(uint32_t*)&h;
}
__device__ __forceinline__ uint32_t pack2(float a, float b) {
    __nv_bfloat162 h = __floats2bfloat162_rn(a, b);
    return *(uint32_t*)&h;
}

// ---------------- LayerNorm (optional bf16 hi/lo split outputs) ----------
__global__ void ln_kernel(const float* __restrict__ x,
                          const float* __restrict__ gamma,
                          const float* __restrict__ beta,
                          float* __restrict__ out,
                          __nv_bfloat16* __restrict__ hi,
                          __nv_bfloat16* __restrict__ lo) {
    __shared__ float sred[8];
    int row = blockIdx.x;
    int t = threadIdx.x;
    const float4* xr = (const float4*)(x + (size_t)row * F_);
    float4 v = xr[t];

    float s = v.x + v.y + v.z + v.w;
    #pragma unroll
    for (int o = 16; o; o >>= 1) s += __shfl_xor_sync(0xffffffffu, s, o);
    if ((t & 31) == 0) sred[t >> 5] = s;
    __syncthreads();
    float tot = 0.f;
    #pragma unroll
    for (int i = 0; i < 8; i++) tot += sred[i];
    float mean = tot * (1.0f / F_);
    __syncthreads();

    float dx = v.x - mean, dy = v.y - mean, dz = v.z - mean, dw = v.w - mean;
    float ss = dx*dx + dy*dy + dz*dz + dw*dw;
    #pragma unroll
    for (int o = 16; o; o >>= 1) ss += __shfl_xor_sync(0xffffffffu, ss, o);
    if ((t & 31) == 0) sred[t >> 5] = ss;
    __syncthreads();
    float tot2 = 0.f;
    #pragma unroll
    for (int i = 0; i < 8; i++) tot2 += sred[i];
    float rstd = rsqrtf(tot2 * (1.0f / F_) + 1e-6f);

    float4 g4 = ((const float4*)gamma)[t];
    float4 b4 = ((const float4*)beta)[t];
    float4 o4;
    o4.x = dx * rstd * g4.x + b4.x;
    o4.y = dy * rstd * g4.y + b4.y;
    o4.z = dz * rstd * g4.z + b4.z;
    o4.w = dw * rstd * g4.w + b4.w;
    ((float4*)(out + (size_t)row * F_))[t] = o4;
    if (hi) {
        __nv_bfloat16 h0, l0, h1, l1, h2, l2, h3, l3;
        split_f32(o4.x, h0, l0); split_f32(o4.y, h1, l1);
        split_f32(o4.z, h2, l2); split_f32(o4.w, h3, l3);
        size_t base = (size_t)row * F_ + 4 * t;
        *(__nv_bfloat162*)&hi[base]     = __nv_bfloat162(h0, h1);
        *(__nv_bfloat162*)&hi[base + 2] = __nv_bfloat162(h2, h3);
        *(__nv_bfloat162*)&lo[base]     = __nv_bfloat162(l0, l1);
        *(__nv_bfloat162*)&lo[base + 2] = __nv_bfloat162(l2, l3);
    }
}

// ---------------- transpose + split: W[k][n] -> T[n][k] bf16 hi/lo -------
__global__ void transpose_split_kernel(const float* __restrict__ W,
                                       __nv_bfloat16* __restrict__ hiT,
                                       __nv_bfloat16* __restrict__ loT) {
    __shared__ float t[32][33];
    int bx = blockIdx.x * 32;  // n
    int by = blockIdx.y * 32;  // k
    int tx = threadIdx.x, ty = threadIdx.y;
    #pragma unroll
    for (int i = 0; i < 4; i++)
        t[ty + 8 * i][tx] = W[(size_t)(by + ty + 8 * i) * F_ + bx + tx];
    __syncthreads();
    #pragma unroll
    for (int i = 0; i < 4; i++) {
        float v = t[tx][ty + 8 * i];
        __nv_bfloat16 h, l;
        split_f32(v, h, l);
        size_t o = (size_t)(bx + ty + 8 * i) * F_ + by + tx;
        hiT[o] = h;
        loT[o] = l;
    }
}

// ---------------- mma.sync GEMM (fp32 out and/or bf16-split out) ---------
#define GBK 32
#define KPAD 40

__global__ __launch_bounds__(256, 2)
void gemm_mma(const __nv_bfloat16* __restrict__ Ahi,
              const __nv_bfloat16* __restrict__ Alo,
              const __nv_bfloat16* __restrict__ BhiT,
              const __nv_bfloat16* __restrict__ BloT,
              const float* __restrict__ bias,
              const float* __restrict__ pos,   // null or [S_, D_]
              const float* __restrict__ res,   // null or [M_, F_]
              float* __restrict__ C,           // nullable fp32 out
              __nv_bfloat16* __restrict__ Chi, // nullable bf16-split out
              __nv_bfloat16* __restrict__ Clo) {
    __shared__ __nv_bfloat16 sAhi[128][KPAD];
    __shared__ __nv_bfloat16 sAlo[128][KPAD];
    __shared__ __nv_bfloat16 sBhi[128][KPAD];
    __shared__ __nv_bfloat16 sBlo[128][KPAD];

    int tid = threadIdx.x;
    int warp = tid >> 5, lane = tid & 31;
    int m0 = blockIdx.y * 128;
    int n0 = blockIdx.x * 128;
    int mw = (warp >> 1) * 32;
    int nw = (warp & 1) * 64;

    float acc[2][8][4];
    #pragma unroll
    for (int i = 0; i < 2; i++)
        #pragma unroll
        for (int j = 0; j < 8; j++)
            #pragma unroll
            for (int c = 0; c < 4; c++) acc[i][j][c] = 0.f;

    int a_row = (lane & 15);
    int a_col = (lane & 16) >> 1;
    int b_row = (lane & 7) + ((lane & 16) >> 1);
    int b_col = (lane & 8);

    for (int kc = 0; kc < F_; kc += GBK) {
        #pragma unroll
        for (int i = 0; i < 2; i++) {
            int f = tid + 256 * i;
            int r = f >> 2, g = f & 3;
            size_t asrc = (size_t)(m0 + r) * F_ + kc + g * 8;
            size_t bsrc = (size_t)(n0 + r) * F_ + kc + g * 8;
            *(uint4*)&sAhi[r][g * 8] = *(const uint4*)(Ahi + asrc);
            *(uint4*)&sAlo[r][g * 8] = *(const uint4*)(Alo + asrc);
            *(uint4*)&sBhi[r][g * 8] = *(const uint4*)(BhiT + bsrc);
            *(uint4*)&sBlo[r][g * 8] = *(const uint4*)(BloT + bsrc);
        }
        __syncthreads();

        #pragma unroll
        for (int ks = 0; ks < 2; ks++) {
            int k0 = ks * 16;
            uint32_t ah[2][4], al[2][4];
            #pragma unroll
            for (int mi = 0; mi < 2; mi++) {
                ldsm4(ah[mi], smem_u32(&sAhi[mw + 16 * mi + a_row][k0 + a_col]));
                ldsm4(al[mi], smem_u32(&sAlo[mw + 16 * mi + a_row][k0 + a_col]));
            }
            #pragma unroll
            for (int ni = 0; ni < 4; ni++) {
                uint32_t bh[4], bl[4];
                ldsm4(bh, smem_u32(&sBhi[nw + 16 * ni + b_row][k0 + b_col]));
                ldsm4(bl, smem_u32(&sBlo[nw + 16 * ni + b_row][k0 + b_col]));
                #pragma unroll
                for (int mi = 0; mi < 2; mi++) {
                    mma_bf16(acc[mi][2 * ni + 0], ah[mi], bh[0], bh[1]);
                    mma_bf16(acc[mi][2 * ni + 0], al[mi], bh[0], bh[1]);
                    mma_bf16(acc[mi][2 * ni + 0], ah[mi], bl[0], bl[1]);
                    mma_bf16(acc[mi][2 * ni + 1], ah[mi], bh[2], bh[3]);
                    mma_bf16(acc[mi][2 * ni + 1], al[mi], bh[2], bh[3]);
                    mma_bf16(acc[mi][2 * ni + 1], ah[mi], bl[2], bl[3]);
                }
            }
        }
        __syncthreads();
    }

    int gid = lane >> 2, tig = lane & 3;
    #pragma unroll
    for (int mi = 0; mi < 2; mi++) {
        #pragma unroll
        for (int nj = 0; nj < 8; nj++) {
            int row = m0 + mw + 16 * mi + gid;
            int col = n0 + nw + 8 * nj + 2 * tig;
            #pragma unroll
            for (int half = 0; half < 2; half++) {
                int r = row + half * 8;
                int s = r & (S_ - 1);
                float v0 = acc[mi][nj][half * 2 + 0] + bias[col];
                float v1 = acc[mi][nj][half * 2 + 1] + bias[col + 1];
                if (pos) {
                    v0 += pos[(size_t)s * D_ + (col & (D_ - 1))];
                    v1 += pos[(size_t)s * D_ + ((col + 1) & (D_ - 1))];
                }
                if (res) {
                    v0 += res[(size_t)r * F_ + col];
                    v1 += res[(size_t)r * F_ + col + 1];
                }
                if (C)
                    *(float2*)&C[(size_t)r * F_ + col] = make_float2(v0, v1);
                if (Chi) {
                    __nv_bfloat16 h0, l0, h1, l1;
                    split_f32(v0, h0, l0); split_f32(v1, h1, l1);
                    *(__nv_bfloat162*)&Chi[(size_t)r * F_ + col] = __nv_bfloat162(h0, h1);
                    *(__nv_bfloat162*)&Clo[(size_t)r * F_ + col] = __nv_bfloat162(l0, l1);
                }
            }
        }
    }
}

// ---------------- Flash attention via mma.sync ---------------------------
// Block: 128 q-rows, key tiles of 64. 8 warps, each warp 16 q-rows x 64 keys.
// No max-subtraction (p = exp(s) exactly; fp32-safe). Writes unnormalized p
// to attn, 1/rowsum to rs, normalized ctx (bf16 hi/lo split) to ctxh/ctxl.
#define FKP 72
#define FLASH_SMEM_BYTES ((2*128*FKP + 4*64*FKP) * 2)

__global__ __launch_bounds__(256, 1)
void flash_mma(const __nv_bfloat16* __restrict__ qh_g, const __nv_bfloat16* __restrict__ ql_g,
               const __nv_bfloat16* __restrict__ kh_g, const __nv_bfloat16* __restrict__ kl_g,
               const __nv_bfloat16* __restrict__ vh_g, const __nv_bfloat16* __restrict__ vl_g,
               float* __restrict__ attn,
               __nv_bfloat16* __restrict__ ctxh, __nv_bfloat16* __restrict__ ctxl,
               float* __restrict__ rs_g) {
    extern __shared__ __nv_bfloat16 fsm[];
    __nv_bfloat16* sQh = fsm;                     // [128][FKP]
    __nv_bfloat16* sQl = fsm + 128 * FKP;
    __nv_bfloat16* sKh = fsm + 2 * 128 * FKP;     // [64][FKP]
    __nv_bfloat16* sKl = sKh + 64 * FKP;
    __nv_bfloat16* sVh = sKh + 2 * 64 * FKP;      // [64 d][FKP keys] (transposed)
    __nv_bfloat16* sVl = sVh + 64 * FKP;

    int tid = threadIdx.x;
    int warp = tid >> 5, lane = tid & 31;
    int gid = lane >> 2, tig = lane & 3;
    int bh = blockIdx.y;
    int b = bh >> 4, h = bh & 15;
    int q0 = blockIdx.x * 128;

    // load Q tiles (hi/lo)
    #pragma unroll
    for (int i = 0; i < 4; i++) {
        int f = tid + 256 * i;
        int r = f >> 3, g = f & 7;
        size_t src = (size_t)(b * S_ + q0 + r) * F_ + h * D_ + g * 8;
        *(uint4*)&sQh[r * FKP + g * 8] = *(const uint4*)(qh_g + src);
        *(uint4*)&sQl[r * FKP + g * 8] = *(const uint4*)(ql_g + src);
    }
    __syncthreads();

    // preload Q fragments (reused for every key tile)
    int a_row = lane & 15, a_col = (lane & 16) >> 1;
    int b_row = (lane & 7) + ((lane & 16) >> 1), b_col = lane & 8;
    uint32_t qfh[4][4], qfl[4][4];
    #pragma unroll
    for (int ks = 0; ks < 4; ks++) {
        ldsm4(qfh[ks], smem_u32(&sQh[(16 * warp + a_row) * FKP + 16 * ks + a_col]));
        ldsm4(qfl[ks], smem_u32(&sQl[(16 * warp + a_row) * FKP + 16 * ks + a_col]));
    }

    float O[8][4];
    #pragma unroll
    for (int i = 0; i < 8; i++)
        #pragma unroll
        for (int c = 0; c < 4; c++) O[i][c] = 0.f;
    float ls0 = 0.f, ls1 = 0.f;

    int r0 = q0 + 16 * warp + gid;
    int r1 = r0 + 8;
    size_t arow0 = (size_t)(bh * S_ + r0) * S_;
    size_t arow1 = (size_t)(bh * S_ + r1) * S_;

    for (int jb = 0; jb < q0 + 128; jb += 64) {
        __syncthreads();
        // load K (hi/lo) row-major [key][d]
        #pragma unroll
        for (int i = 0; i < 2; i++) {
            int f = tid + 256 * i;
            int r = f >> 3, g = f & 7;
            size_t src = (size_t)(b * S_ + jb + r) * F_ + h * D_ + g * 8;
            *(uint4*)&sKh[r * FKP + g * 8] = *(const uint4*)(kh_g + src);
            *(uint4*)&sKl[r * FKP + g * 8] = *(const uint4*)(kl_g + src);
        }
        // load V transposed: [d][key]
        #pragma unroll
        for (int i = 0; i < 8; i++) {
            int idx = tid + 256 * i;
            int key = idx >> 5, dp = idx & 31;
            size_t src = (size_t)(b * S_ + jb + key) * F_ + h * D_ + 2 * dp;
            __nv_bfloat162 vh2 = *(const __nv_bfloat162*)(vh_g + src);
            __nv_bfloat162 vl2 = *(const __nv_bfloat162*)(vl_g + src);
            sVh[(2 * dp + 0) * FKP + key] = vh2.x;
            sVh[(2 * dp + 1) * FKP + key] = vh2.y;
            sVl[(2 * dp + 0) * FKP + key] = vl2.x;
            sVl[(2 * dp + 1) * FKP + key] = vl2.y;
        }
        __syncthreads();

        // QK^T: S fragments [8 n-tiles][4]
        float Sv[8][4];
        #pragma unroll
        for (int i = 0; i < 8; i++)
            Sv[i][0] = Sv[i][1] = Sv[i][2] = Sv[i][3] = 0.f;
        #pragma unroll
        for (int ks = 0; ks < 4; ks++) {
            #pragma unroll
            for (int ni = 0; ni < 4; ni++) {
                uint32_t kbh[4], kbl[4];
                ldsm4(kbh, smem_u32(&sKh[(16 * ni + b_row) * FKP + 16 * ks + b_col]));
                ldsm4(kbl, smem_u32(&sKl[(16 * ni + b_row) * FKP + 16 * ks + b_col]));
                mma_bf16(Sv[2 * ni + 0], qfh[ks], kbh[0], kbh[1]);
                mma_bf16(Sv[2 * ni + 0], qfl[ks], kbh[0], kbh[1]);
                mma_bf16(Sv[2 * ni + 0], qfh[ks], kbl[0], kbl[1]);
                mma_bf16(Sv[2 * ni + 1], qfh[ks], kbh[2], kbh[3]);
                mma_bf16(Sv[2 * ni + 1], qfl[ks], kbh[2], kbh[3]);
                mma_bf16(Sv[2 * ni + 1], qfh[ks], kbl[2], kbl[3]);
            }
        }

        // exp + mask + attn write + rowsum (in-place Sv -> p)
        bool needmask = (jb + 63 > q0 + 16 * warp);
        #pragma unroll
        for (int nt = 0; nt < 8; nt++) {
            int c0 = jb + 8 * nt + 2 * tig;
            float e0 = fexp_dot(Sv[nt][0]);
            float e1 = fexp_dot(Sv[nt][1]);
            float e2 = fexp_dot(Sv[nt][2]);
            float e3 = fexp_dot(Sv[nt][3]);
            if (needmask) {
                if (c0 + 0 > r0) e0 = 0.f;
                if (c0 + 1 > r0) e1 = 0.f;
                if (c0 + 0 > r1) e2 = 0.f;
                if (c0 + 1 > r1) e3 = 0.f;
            }
            Sv[nt][0] = e0; Sv[nt][1] = e1; Sv[nt][2] = e2; Sv[nt][3] = e3;
            __stcs((float2*)&attn[arow0 + c0], make_float2(e0, e1));
            __stcs((float2*)&attn[arow1 + c0], make_float2(e2, e3));
            ls0 += e0 + e1;
            ls1 += e2 + e3;
        }

        // P @ V (P fragments from Sv, 3-product split)
        #pragma unroll
        for (int kt = 0; kt < 4; kt++) {
            float ra, rb;
            uint32_t pah[4], pal[4];
            float lo0, lo1, lo2, lo3;
            pah[0] = pack_hi(Sv[2 * kt][0], Sv[2 * kt][1], lo0, lo1);
            pal[0] = pack2(lo0, lo1);
            pah[1] = pack_hi(Sv[2 * kt][2], Sv[2 * kt][3], lo0, lo1);
            pal[1] = pack2(lo0, lo1);
            pah[2] = pack_hi(Sv[2 * kt + 1][0], Sv[2 * kt + 1][1], lo2, lo3);
            pal[2] = pack2(lo2, lo3);
            pah[3] = pack_hi(Sv[2 * kt + 1][2], Sv[2 * kt + 1][3], lo2, lo3);
            pal[3] = pack2(lo2, lo3);
            (void)ra; (void)rb;
            #pragma unroll
            for (int ni = 0; ni < 4; ni++) {
                uint32_t vbh[4], vbl[4];
                ldsm4(vbh, smem_u32(&sVh[(16 * ni + b_row) * FKP + 16 * kt + b_col]));
                ldsm4(vbl, smem_u32(&sVl[(16 * ni + b_row) * FKP + 16 * kt + b_col]));
                mma_bf16(O[2 * ni + 0], pah, vbh[0], vbh[1]);
                mma_bf16(O[2 * ni + 0], pal, vbh[0], vbh[1]);
                mma_bf16(O[2 * ni + 0], pah, vbl[0], vbl[1]);
                mma_bf16(O[2 * ni + 1], pah, vbh[2], vbh[3]);
                mma_bf16(O[2 * ni + 1], pal, vbh[2], vbh[3]);
                mma_bf16(O[2 * ni + 1], pah, vbl[2], vbl[3]);
            }
        }
    }

    // rowsum reduce over tig lanes (warp owns full rows)
    ls0 += __shfl_xor_sync(0xffffffffu, ls0, 1);
    ls0 += __shfl_xor_sync(0xffffffffu, ls0, 2);
    ls1 += __shfl_xor_sync(0xffffffffu, ls1, 1);
    ls1 += __shfl_xor_sync(0xffffffffu, ls1, 2);
    float rs0 = 1.0f / ls0, rs1 = 1.0f / ls1;
    if (tig == 0) {
        rs_g[bh * S_ + r0] = rs0;
        rs_g[bh * S_ + r1] = rs1;
    }

    // ctx out (bf16 hi/lo split)
    #pragma unroll
    for (int nt = 0; nt < 8; nt++) {
        int col = h * D_ + 8 * nt + 2 * tig;
        float o0 = O[nt][0] * rs0, o1 = O[nt][1] * rs0;
        float o2 = O[nt][2] * rs1, o3 = O[nt][3] * rs1;
        __nv_bfloat16 h0, l0, h1, l1;
        split_f32(o0, h0, l0); split_f32(o1, h1, l1);
        *(__nv_bfloat162*)&ctxh[(size_t)(b * S_ + r0) * F_ + col] = __nv_bfloat162(h0, h1);
        *(__nv_bfloat162*)&ctxl[(size_t)(b * S_ + r0) * F_ + col] = __nv_bfloat162(l0, l1);
        split_f32(o2, h0, l0); split_f32(o3, h1, l1);
        *(__nv_bfloat162*)&ctxh[(size_t)(b * S_ + r1) * F_ + col] = __nv_bfloat162(h0, h1);
        *(__nv_bfloat162*)&ctxl[(size_t)(b * S_ + r1) * F_ + col] = __nv_bfloat162(l0, l1);
    }
}

// ---------------- rescale: attn *= 1/rowsum; zero masked triangle --------
__global__ void rescale_kernel(float* __restrict__ attn,
                               const float* __restrict__ rs) {
    size_t stride = (size_t)gridDim.x * blockDim.x;
    const size_t total = ATTN_ELEMS / 4;
    for (size_t f = (size_t)blockIdx.x * blockDim.x + threadIdx.x; f < total; f += stride) {
        int col4 = (int)(f & (S_ / 4 - 1));
        int row  = (int)((f >> 9) & (S_ - 1));
        int bh   = (int)(f >> 20);
        int col0 = col4 << 2;
        float4* p = (float4*)attn + f;
        if (col0 > row) {
            __stcs(p, make_float4(0.f, 0.f, 0.f, 0.f));
        } else {
            float c = __ldg(&rs[bh * S_ + row]);
            float4 vv = __ldcs(p);
            vv.x *= c; vv.y *= c; vv.z *= c; vv.w *= c;
            __stcs(p, vv);
        }
    }
}

// ---------------- launch ----------------
extern "C" void kernel_launch(void* const* d_in, const int* in_sizes, int n_in,
                              void* d_out, int out_size) {
    const float* x      = (const float*)d_in[0];
    const float* Wq     = (const float*)d_in[1];
    const float* bq     = (const float*)d_in[2];
    const float* Wk     = (const float*)d_in[3];
    const float* bk     = (const float*)d_in[4];
    const float* Wv     = (const float*)d_in[5];
    const float* bv     = (const float*)d_in[6];
    const float* Wo     = (const float*)d_in[7];
    const float* bo     = (const float*)d_in[8];
    const float* gamma1 = (const float*)d_in[9];
    const float* beta1  = (const float*)d_in[10];
    const float* gamma2 = (const float*)d_in[11];
    const float* beta2  = (const float*)d_in[12];
    const float* pos    = (const float*)d_in[13];

    float* out = (float*)d_out;

    float *xn, *tmp, *rs, *attn_fb;
    cudaGetSymbolAddress((void**)&xn, g_xn);
    cudaGetSymbolAddress((void**)&tmp, g_tmp);
    cudaGetSymbolAddress((void**)&rs, g_rs);
    cudaGetSymbolAddress((void**)&attn_fb, g_attn_fallback);

    __nv_bfloat16 *xnh, *xnl, *qh, *ql, *kh, *kl, *vh, *vl, *ctxh, *ctxl;
    __nv_bfloat16 *wqh, *wql, *wkh, *wkl, *wvh, *wvl, *woh, *wol;
    cudaGetSymbolAddress((void**)&xnh, g_xn_hi);
    cudaGetSymbolAddress((void**)&xnl, g_xn_lo);
    cudaGetSymbolAddress((void**)&qh, g_qh);
    cudaGetSymbolAddress((void**)&ql, g_ql);
    cudaGetSymbolAddress((void**)&kh, g_kh);
    cudaGetSymbolAddress((void**)&kl, g_kl);
    cudaGetSymbolAddress((void**)&vh, g_vh);
    cudaGetSymbolAddress((void**)&vl, g_vl);
    cudaGetSymbolAddress((void**)&ctxh, g_ctx_hi);
    cudaGetSymbolAddress((void**)&ctxl, g_ctx_lo);
    cudaGetSymbolAddress((void**)&wqh, g_WqT_hi);
    cudaGetSymbolAddress((void**)&wql, g_WqT_lo);
    cudaGetSymbolAddress((void**)&wkh, g_WkT_hi);
    cudaGetSymbolAddress((void**)&wkl, g_WkT_lo);
    cudaGetSymbolAddress((void**)&wvh, g_WvT_hi);
    cudaGetSymbolAddress((void**)&wvl, g_WvT_lo);
    cudaGetSymbolAddress((void**)&woh, g_WoT_hi);
    cudaGetSymbolAddress((void**)&wol, g_WoT_lo);

    float* attn = (out_size > OUT_ELEMS) ? (out + OUT_ELEMS) : attn_fb;

    cudaFuncSetAttribute(flash_mma,
                         cudaFuncAttributeMaxDynamicSharedMemorySize,
                         FLASH_SMEM_BYTES);

    // 1) LN1 (with bf16 split outputs) + weight transpose-splits
    ln_kernel<<<M_, 256>>>(x, gamma1, beta1, xn, xnh, xnl);
    dim3 tb(32, 8), tg(F_ / 32, F_ / 32);
    transpose_split_kernel<<<tg, tb>>>(Wq, wqh, wql);
    transpose_split_kernel<<<tg, tb>>>(Wk, wkh, wkl);
    transpose_split_kernel<<<tg, tb>>>(Wv, wvh, wvl);
    transpose_split_kernel<<<tg, tb>>>(Wo, woh, wol);

    // 2) Q/K/V projections -> bf16 hi/lo outputs directly
    dim3 ggrid(F_ / 128, M_ / 128);
    gemm_mma<<<ggrid, 256>>>(xnh, xnl, wqh, wql, bq, nullptr, nullptr, nullptr, qh, ql);
    gemm_mma<<<ggrid, 256>>>(xnh, xnl, wkh, wkl, bk, pos,     nullptr, nullptr, kh, kl);
    gemm_mma<<<ggrid, 256>>>(xnh, xnl, wvh, wvl, bv, nullptr, nullptr, nullptr, vh, vl);

    // 3) flash attention (mma.sync, no-max softmax)
    dim3 fgrid(S_ / 128, BH_);
    flash_mma<<<fgrid, 256, FLASH_SMEM_BYTES>>>(qh, ql, kh, kl, vh, vl,
                                                attn, ctxh, ctxl, rs);

    // 4) normalize attn + zero-fill masked triangle (pure memory op)
    rescale_kernel<<<32768, 256>>>(attn, rs);

    // 5) output projection + residual -> fp32 tmp
    gemm_mma<<<ggrid, 256>>>(ctxh, ctxl, woh, wol, bo, nullptr, xn, tmp, nullptr, nullptr);

    // 6) LN2
    ln_kernel<<<M_, 256>>>(tmp, gamma2, beta2, out, nullptr, nullptr);
}